// round 8
// baseline (speedup 1.0000x reference)
#include <cuda_runtime.h>
#include <cuda_bf16.h>

// NeuronGemma4VisionPooler: B=8, S=4096, H=1152, L=256, k=4, k_sq=16
// hidden_states f32 [B,S,H]; pixel_position_ids i32 [B,S,2];
// padding_positions bool [B,S]; out: pooled f32 [B,L,H] (+ mask [B,L] f32)

#define BB 8
#define SS 4096
#define HH 1152
#define LL 256
#define KK 4
#define CAP 64      // max recorded tokens per bin (expected 16)
#define NCTA 512    // pool CTAs; 4 bins each
#define BPC 4
#define NPREP 64    // prep CTAs (8 per batch)

// Invariants at entry to kernel_launch (first call: .bss zeros; later calls:
// reset inside this kernel): g_count all zero, g_done==0, g_ack==0.
__device__ int g_count[BB * LL];      // packed: [total<<16 | appended]
__device__ int g_inv[BB * LL * CAP];
__device__ unsigned g_done;
__device__ unsigned g_ack;

// Single fused kernel. __launch_bounds__(288,4) guarantees >=4 CTAs/SM
// residency (148 SMs * 4 = 592 >= NCTA=512), so the global spin barrier
// between the prep phase and the pool phase cannot deadlock.
__global__ void __launch_bounds__(288, 4)
k_fused(const float* __restrict__ hs, const int* __restrict__ pos,
        const unsigned char* __restrict__ pad, float* __restrict__ out,
        int write_mask) {
    const int c = blockIdx.x;
    const int t = threadIdx.x;
    __shared__ int s_red[9];
    __shared__ int sidx[2][CAP];
    __shared__ int scnt[2];

    // ---------- phase 1: CTAs 0..63 bin their 512-token slice ----------
    if (c < NPREP) {
        const int b = c >> 3, slice = c & 7;
        const int2* __restrict__ p2 = (const int2*)pos + (size_t)b * SS;

        // per-batch max of clamped x (redundant per block; pos is L2-hot)
        int m = 0;
        for (int s = t; s < SS; s += 288) {
            int x = p2[s].x;
            if (x > m) m = x;                   // clip(x,0): negatives lose
        }
        #pragma unroll
        for (int o = 16; o; o >>= 1) m = max(m, __shfl_xor_sync(~0u, m, o));
        if ((t & 31) == 0) s_red[t >> 5] = m;
        __syncthreads();
        if (t < 32) {
            int v = (t < 9) ? s_red[t] : 0;
            #pragma unroll
            for (int o = 8; o; o >>= 1) v = max(v, __shfl_xor_sync(~0u, v, o));
            if (t == 0) s_red[0] = (v + 1) / KK; // (max_clamped+1)/k
        }
        __syncthreads();
        const int mxk = s_red[0];

        for (int j = t; j < 512; j += 288) {
            int s = slice * 512 + j;
            int2 p = p2[s];
            int x = max(p.x, 0);
            int y = max(p.y, 0);
            int idx = x / KK + mxk * (y / KK);
            if (idx < LL) {                      // one_hot drops idx >= L
                if (pad[(size_t)b * SS + s]) {
                    atomicAdd(&g_count[b * LL + idx], 0x10000);  // mask only
                } else {
                    int old = atomicAdd(&g_count[b * LL + idx], 0x10001);
                    int slot = old & 0xffff;
                    if (slot < CAP) g_inv[(b * LL + idx) * CAP + slot] = s;
                }
            }
        }
        __syncthreads();
        if (t == 0) { __threadfence(); atomicAdd(&g_done, 1u); }
    }

    // ---------- global barrier: all prep CTAs done ----------
    if (t == 0) {
        while (atomicAdd(&g_done, 0u) < (unsigned)NPREP) __nanosleep(64);
        __threadfence();
        unsigned a = atomicAdd(&g_ack, 1u);
        if (a == (unsigned)(NCTA - 1)) { g_done = 0u; g_ack = 0u; } // next-launch reset
    }
    __syncthreads();

    // ---------- phase 2: pool BPC bins with pipelined index prefetch ----------
    const float4* __restrict__ hs4 = (const float4*)hs;
    const int bin0 = c * BPC;

    int pidx = 0, pcnt = 0;
    if (t < CAP) pidx = __ldg(&g_inv[bin0 * CAP + t]);
    if (t == CAP) { pcnt = g_count[bin0]; g_count[bin0] = 0; } // reset for next launch
    if (t < CAP) sidx[0][t] = pidx;
    if (t == CAP) scnt[0] = pcnt;

    int cur = 0;
    for (int i = 0; i < BPC; i++) {
        __syncthreads();                         // buffer 'cur' ready
        const int bin = bin0 + i;
        const int packed = scnt[cur];
        const int n = min(packed & 0xffff, CAP);

        // issue next bin's index loads now; commit to smem after accumulation
        if (i + 1 < BPC) {
            const int nb = bin + 1;
            if (t < CAP) pidx = __ldg(&g_inv[nb * CAP + t]);
            if (t == CAP) { pcnt = g_count[nb]; g_count[nb] = 0; }
        }

        const float4* __restrict__ base = hs4 + (size_t)(bin >> 8) * SS * (HH / 4);
        float4 acc = make_float4(0.f, 0.f, 0.f, 0.f);
        if (n == 16) {
            #pragma unroll
            for (int j = 0; j < 16; j++) {
                float4 v = __ldg(&base[(size_t)sidx[cur][j] * (HH / 4) + t]);
                acc.x += v.x; acc.y += v.y; acc.z += v.z; acc.w += v.w;
            }
        } else {
            for (int j = 0; j < n; j++) {
                float4 v = __ldg(&base[(size_t)sidx[cur][j] * (HH / 4) + t]);
                acc.x += v.x; acc.y += v.y; acc.z += v.z; acc.w += v.w;
            }
        }

        const int nxt = cur ^ 1;
        if (i + 1 < BPC) {                        // commit prefetch (other buffer)
            if (t < CAP) sidx[nxt][t] = pidx;
            if (t == CAP) scnt[nxt] = pcnt;
        }

        const float scale = 2.1213203435596424f;  // sqrt(1152)/16
        acc.x *= scale; acc.y *= scale; acc.z *= scale; acc.w *= scale;
        ((float4*)out)[(size_t)bin * (HH / 4) + t] = acc;
        if (write_mask && t == 0)
            out[(size_t)BB * LL * HH + bin] = ((packed >> 16) > 0) ? 1.0f : 0.0f;
        cur = nxt;
    }
}

extern "C" void kernel_launch(void* const* d_in, const int* in_sizes, int n_in,
                              void* d_out, int out_size) {
    const float*         hs  = (const float*)d_in[0];
    const int*           pos = (const int*)d_in[1];
    const unsigned char* pad = (const unsigned char*)d_in[2];
    float* out = (float*)d_out;

    int write_mask = (out_size >= BB * LL * HH + BB * LL) ? 1 : 0;

    k_fused<<<NCTA, 288>>>(hs, pos, pad, out, write_mask);
}

// round 9
// speedup vs baseline: 1.2929x; 1.2929x over previous
#include <cuda_runtime.h>
#include <cuda_bf16.h>

// NeuronGemma4VisionPooler: B=8, S=4096, H=1152, L=256, k=4, k_sq=16
// hidden_states f32 [B,S,H]; pixel_position_ids i32 [B,S,2];
// padding_positions bool [B,S]; out: pooled f32 [B,L,H] (+ mask [B,L] f32)

#define BB 8
#define SS 4096
#define HH 1152
#define LL 256
#define KK 4
#define CAP 64        // max recorded tokens per bin (expected 16)
#define NPREP 64      // prep CTAs (8 per batch) -- all in wave 1
#define NCTA (BB*LL)  // 2048: one CTA per output bin (same as R7 k_pool)

// Invariants at entry to kernel_launch (first call: .bss zeros; later calls:
// reset inside this kernel): g_count all zero, g_done==0, g_ack==0.
__device__ int g_count[BB * LL];      // packed: [total<<16 | appended]
__device__ int g_inv[BB * LL * CAP];
__device__ volatile unsigned g_done;  // prep CTAs completed
__device__ unsigned g_ack;            // pool CTAs past barrier (for reset)

// Fused kernel, grid = 2048 (one bin per CTA, identical pool body to R7).
// CTAs 0..63 run the binning prologue first; everyone then waits on a
// read-only spin of g_done. Prep CTAs are block ids 0..63 => guaranteed in
// scheduling wave 1 (740 resident CTAs at 5/SM) and depend on no other CTA,
// so the spin cannot deadlock.
__global__ void __launch_bounds__(288, 5)
k_fused(const float* __restrict__ hs, const int* __restrict__ pos,
        const unsigned char* __restrict__ pad, float* __restrict__ out,
        int write_mask) {
    const int c = blockIdx.x;
    const int t = threadIdx.x;
    __shared__ int s_red[9];
    __shared__ int sidx[CAP];

    // ---------- phase 1: CTAs 0..63 bin their 512-token slice ----------
    if (c < NPREP) {
        const int b = c >> 3, slice = c & 7;
        const int2* __restrict__ p2 = (const int2*)pos + (size_t)b * SS;

        // per-batch max of clamped x (redundant per block; pos is tiny/L2)
        int m = 0;
        for (int s = t; s < SS; s += 288) {
            int x = p2[s].x;
            if (x > m) m = x;                    // clip(x,0): negatives lose
        }
        #pragma unroll
        for (int o = 16; o; o >>= 1) m = max(m, __shfl_xor_sync(~0u, m, o));
        if ((t & 31) == 0) s_red[t >> 5] = m;
        __syncthreads();
        if (t < 32) {
            int v = (t < 9) ? s_red[t] : 0;
            #pragma unroll
            for (int o = 8; o; o >>= 1) v = max(v, __shfl_xor_sync(~0u, v, o));
            if (t == 0) s_red[0] = (v + 1) / KK; // (max_clamped+1)/k
        }
        __syncthreads();
        const int mxk = s_red[0];

        for (int j = t; j < 512; j += 288) {
            int s = slice * 512 + j;
            int2 p = p2[s];
            int x = max(p.x, 0);
            int y = max(p.y, 0);
            int idx = x / KK + mxk * (y / KK);
            if (idx < LL) {                       // one_hot drops idx >= L
                if (pad[(size_t)b * SS + s]) {
                    atomicAdd(&g_count[b * LL + idx], 0x10000);  // mask only
                } else {
                    int old = atomicAdd(&g_count[b * LL + idx], 0x10001);
                    int slot = old & 0xffff;
                    if (slot < CAP) g_inv[(b * LL + idx) * CAP + slot] = s;
                }
            }
        }
        __syncthreads();
        if (t == 0) { __threadfence(); atomicAdd((unsigned*)&g_done, 1u); }
    }

    // ---------- barrier: wait for all prep CTAs (read-only spin) ----------
    if (t == 0) {
        while (g_done < (unsigned)NPREP) __nanosleep(32);
        __threadfence();                          // acquire
    }
    __syncthreads();

    // ---------- phase 2: pool one bin (identical structure to R7) ----------
    const int b = c >> 8;
    const int l = c & (LL - 1);
    const int packed = g_count[c];
    const int n = min(packed & 0xffff, CAP);
    const float4* __restrict__ hs4 =
        (const float4*)hs + (size_t)b * SS * (HH / 4);

    if (t < n) sidx[t] = g_inv[c * CAP + t];
    __syncthreads();
    if (t == 0) g_count[c] = 0;                   // reset for next launch

    float4 acc = make_float4(0.f, 0.f, 0.f, 0.f);
    if (n == 16) {
        #pragma unroll
        for (int j = 0; j < 16; j++) {
            float4 v = __ldg(&hs4[(size_t)sidx[j] * (HH / 4) + t]);
            acc.x += v.x; acc.y += v.y; acc.z += v.z; acc.w += v.w;
        }
    } else {
        for (int j = 0; j < n; j++) {
            float4 v = __ldg(&hs4[(size_t)sidx[j] * (HH / 4) + t]);
            acc.x += v.x; acc.y += v.y; acc.z += v.z; acc.w += v.w;
        }
    }
    const float scale = 2.1213203435596424f;      // sqrt(1152)/16
    acc.x *= scale; acc.y *= scale; acc.z *= scale; acc.w *= scale;
    ((float4*)out)[(size_t)c * (HH / 4) + t] = acc;

    if (write_mask && t == 0)
        out[(size_t)BB * LL * HH + c] = ((packed >> 16) > 0) ? 1.0f : 0.0f;

    // ---------- flag reset: last CTA through restores launch invariants ----
    if (t == 0) {
        unsigned a = atomicAdd(&g_ack, 1u);
        if (a == (unsigned)(NCTA - 1)) { g_done = 0u; g_ack = 0u; }
    }
}

extern "C" void kernel_launch(void* const* d_in, const int* in_sizes, int n_in,
                              void* d_out, int out_size) {
    const float*         hs  = (const float*)d_in[0];
    const int*           pos = (const int*)d_in[1];
    const unsigned char* pad = (const unsigned char*)d_in[2];
    float* out = (float*)d_out;

    int write_mask = (out_size >= BB * LL * HH + BB * LL) ? 1 : 0;

    k_fused<<<NCTA, 288>>>(hs, pos, pad, out, write_mask);
}

// round 10
// speedup vs baseline: 1.6203x; 1.2532x over previous
#include <cuda_runtime.h>
#include <cuda_bf16.h>

// NeuronGemma4VisionPooler: B=8, S=4096, H=1152, L=256, k=4, k_sq=16
// hidden_states f32 [B,S,H]; pixel_position_ids i32 [B,S,2];
// padding_positions bool [B,S]; out: pooled f32 [B,L,H] (+ mask [B,L] f32)

#define BB 8
#define SS 4096
#define HH 1152
#define LL 256
#define KK 4
#define CAP 64   // max recorded tokens per output bin (expected 16)

// Invariant: g_count is all-zero at entry to kernel_launch.
// (.bss zero at module load for the 1st call; k_pool resets it every call.)
__device__ int g_count[BB * LL];            // packed: [total<<16 | appended]
__device__ int g_inv[BB * LL * CAP];

// --- K1: parallel prologue. 8 blocks per batch (64 total).
// Each block: redundant max_x reduce over its whole batch (L2-resident),
// then bins exactly its 512-token slice via global packed atomics.
__global__ void __launch_bounds__(512)
k_prep(const int* __restrict__ pos, const unsigned char* __restrict__ pad) {
    const int b     = blockIdx.x >> 3;
    const int slice = blockIdx.x & 7;
    const int t     = threadIdx.x;
    const int2* __restrict__ p2 = (const int2*)pos + (size_t)b * SS;

    // max over clamped x for the whole batch
    int m = 0;
    #pragma unroll
    for (int s = t; s < SS; s += 512) {
        int x = p2[s].x;
        if (x > m) m = x;                      // clip(x,0): negatives lose
    }
    #pragma unroll
    for (int o = 16; o; o >>= 1) m = max(m, __shfl_xor_sync(0xffffffffu, m, o));
    __shared__ int s_red[16];
    __shared__ int s_mxk;
    if ((t & 31) == 0) s_red[t >> 5] = m;
    __syncthreads();
    if (t < 16) {
        int v = s_red[t];
        #pragma unroll
        for (int o = 8; o; o >>= 1) v = max(v, __shfl_xor_sync(0xffffu, v, o));
        if (t == 0) s_mxk = (v + 1) / KK;       // (max_clamped+1)/k
    }
    __syncthreads();
    const int mxk = s_mxk;

    // bin this block's 512-token slice (one token per thread)
    const int s = slice * 512 + t;
    int2 p = p2[s];
    int x = max(p.x, 0);
    int y = max(p.y, 0);
    int idx = x / KK + mxk * (y / KK);
    if (idx < LL) {                             // one_hot drops idx >= L
        if (pad[(size_t)b * SS + s]) {
            atomicAdd(&g_count[b * LL + idx], 0x10000);   // total only (mask)
        } else {
            int old = atomicAdd(&g_count[b * LL + idx], 0x10001);
            int slot = old & 0xffff;
            if (slot < CAP)
                g_inv[(b * LL + idx) * CAP + slot] = s;
        }
    }
}

// --- K2: gather-reduce rows per output bin; resets its counter for the
// next kernel_launch invocation (graph replay safety).
// (288,6): forces regs<=37 -> 6 CTAs/SM, 54 warps (84% occ), 2.31 waves.
__global__ void __launch_bounds__(288, 6)
k_pool(const float* __restrict__ hs, float* __restrict__ out, int write_mask) {
    const int b = blockIdx.x >> 8;
    const int l = blockIdx.x & (LL - 1);
    const int t = threadIdx.x;                  // 0..287 = H/4 lanes
    const int packed = g_count[b * LL + l];
    const int n = min(packed & 0xffff, CAP);
    const float4* __restrict__ hs4 =
        (const float4*)hs + (size_t)b * SS * (HH / 4);

    __shared__ int sidx[CAP];
    if (t < n) sidx[t] = g_inv[(b * LL + l) * CAP + t];
    __syncthreads();
    if (t == 0) g_count[b * LL + l] = 0;        // reset for next launch

    float4 acc = make_float4(0.f, 0.f, 0.f, 0.f);
    if (n == 16) {
        // common case: fully unrolled, loads batched in flight
        #pragma unroll
        for (int j = 0; j < 16; j++) {
            float4 v = __ldg(&hs4[(size_t)sidx[j] * (HH / 4) + t]);
            acc.x += v.x; acc.y += v.y; acc.z += v.z; acc.w += v.w;
        }
    } else {
        for (int j = 0; j < n; j++) {
            float4 v = __ldg(&hs4[(size_t)sidx[j] * (HH / 4) + t]);
            acc.x += v.x; acc.y += v.y; acc.z += v.z; acc.w += v.w;
        }
    }
    const float scale = 2.1213203435596424f;    // sqrt(1152)/16
    acc.x *= scale; acc.y *= scale; acc.z *= scale; acc.w *= scale;
    ((float4*)out)[(size_t)(b * LL + l) * (HH / 4) + t] = acc;

    if (write_mask && t == 0)
        out[(size_t)BB * LL * HH + b * LL + l] =
            ((packed >> 16) > 0) ? 1.0f : 0.0f;
}

extern "C" void kernel_launch(void* const* d_in, const int* in_sizes, int n_in,
                              void* d_out, int out_size) {
    const float*         hs  = (const float*)d_in[0];
    const int*           pos = (const int*)d_in[1];
    const unsigned char* pad = (const unsigned char*)d_in[2];
    float* out = (float*)d_out;

    int write_mask = (out_size >= BB * LL * HH + BB * LL) ? 1 : 0;

    k_prep<<<BB * 8, 512>>>(pos, pad);
    k_pool<<<BB * LL, 288>>>(hs, out, write_mask);
}